// round 2
// baseline (speedup 1.0000x reference)
#include <cuda_runtime.h>

// CFConv fused kernel, fp32 baseline.
// h  = softplus_b05(rbf @ W1^T + b1)      [E,128]x[64,128]^T -> [E,64]
// g  = h @ W2^T + b2                      [E,64]x[64,64]^T   -> [E,64]
// out[dst[e]] += node_feats[src[e]] * g[e]
//
// Tiling: 64 edges x 64 dims per 256-thread block, BK=16, 4x4 register tile.

constexpr int R_DIM = 128;   // RBF dim (K of GEMM1)
constexpr int D_DIM = 64;    // feature dim
constexpr int BM = 64;       // edges per tile
constexpr int BN = 64;       // output dims per tile (== D_DIM)
constexpr int BK = 16;       // k-chunk

__global__ void zero_out_kernel(float4* out4, int n4) {
    int i = blockIdx.x * blockDim.x + threadIdx.x;
    if (i < n4) out4[i] = make_float4(0.f, 0.f, 0.f, 0.f);
}

__device__ __forceinline__ float softplus_b05(float x) {
    // (1/0.5)*log(1+exp(0.5*x)), linear when 0.5*x > 14
    float hx = 0.5f * x;
    return (hx > 14.0f) ? x : 2.0f * log1pf(__expf(hx));
}

__global__ __launch_bounds__(256, 2) void cfconv_kernel(
    const float* __restrict__ rbf,   // [E,128]
    const float* __restrict__ nf,    // [N,64]
    const int*   __restrict__ src,   // [E]
    const int*   __restrict__ dst,   // [E]
    const float* __restrict__ W1,    // [64,128]
    const float* __restrict__ b1,    // [64]
    const float* __restrict__ W2,    // [64,64]
    const float* __restrict__ b2,    // [64]
    float*       __restrict__ out,   // [N,64]
    int E)
{
    __shared__ float As[BK][BM];        // rbf chunk, k-major
    __shared__ float Bs[BK][BN];        // W chunk,  k-major
    __shared__ float sH[BM][BN + 4];    // softplus(h) tile
    __shared__ int   sSrc[BM];
    __shared__ int   sDst[BM];

    const int tid = threadIdx.x;
    const int tx  = tid & 15;           // n-direction (dims),  cols tx*4..+3
    const int ty  = tid >> 4;           // m-direction (edges), rows ty*4..+3
    const long e0 = (long)blockIdx.x * BM;

    if (tid < BM) {
        long e = e0 + tid;
        sSrc[tid] = (e < E) ? src[e] : 0;
        sDst[tid] = (e < E) ? dst[e] : 0;
    }

    // global-load mapping for smem tiles: each thread loads one float4
    const int le = tid >> 2;            // row 0..63 (edge for As, weight-row for Bs)
    const int lk = (tid & 3) << 2;      // k offset within chunk: 0,4,8,12
    const long eL = e0 + le;
    const bool evalid = (eL < E);

    float acc[4][4] = {};

    // ---------------- GEMM1: h = rbf @ W1^T ----------------
    for (int kc = 0; kc < R_DIM; kc += BK) {
        float4 av = evalid ? *(const float4*)(rbf + eL * R_DIM + kc + lk)
                           : make_float4(0.f, 0.f, 0.f, 0.f);
        float4 bv = *(const float4*)(W1 + (long)le * R_DIM + kc + lk);
        As[lk + 0][le] = av.x; As[lk + 1][le] = av.y;
        As[lk + 2][le] = av.z; As[lk + 3][le] = av.w;
        Bs[lk + 0][le] = bv.x; Bs[lk + 1][le] = bv.y;
        Bs[lk + 2][le] = bv.z; Bs[lk + 3][le] = bv.w;
        __syncthreads();
        #pragma unroll
        for (int k = 0; k < BK; k++) {
            float4 a4 = *(const float4*)&As[k][ty << 2];
            float4 b4 = *(const float4*)&Bs[k][tx << 2];
            acc[0][0] += a4.x * b4.x; acc[0][1] += a4.x * b4.y;
            acc[0][2] += a4.x * b4.z; acc[0][3] += a4.x * b4.w;
            acc[1][0] += a4.y * b4.x; acc[1][1] += a4.y * b4.y;
            acc[1][2] += a4.y * b4.z; acc[1][3] += a4.y * b4.w;
            acc[2][0] += a4.z * b4.x; acc[2][1] += a4.z * b4.y;
            acc[2][2] += a4.z * b4.z; acc[2][3] += a4.z * b4.w;
            acc[3][0] += a4.w * b4.x; acc[3][1] += a4.w * b4.y;
            acc[3][2] += a4.w * b4.z; acc[3][3] += a4.w * b4.w;
        }
        __syncthreads();
    }

    // bias + softplus, stage h tile in smem
    {
        float4 b1v = *(const float4*)(b1 + (tx << 2));
        #pragma unroll
        for (int i = 0; i < 4; i++) {
            int r = (ty << 2) + i;
            float4 h4;
            h4.x = softplus_b05(acc[i][0] + b1v.x);
            h4.y = softplus_b05(acc[i][1] + b1v.y);
            h4.z = softplus_b05(acc[i][2] + b1v.z);
            h4.w = softplus_b05(acc[i][3] + b1v.w);
            *(float4*)&sH[r][tx << 2] = h4;
        }
    }
    __syncthreads();

    // ---------------- GEMM2: g = h @ W2^T ----------------
    float acc2[4][4] = {};
    for (int kc = 0; kc < D_DIM; kc += BK) {
        float4 bv = *(const float4*)(W2 + (long)le * D_DIM + kc + lk);
        Bs[lk + 0][le] = bv.x; Bs[lk + 1][le] = bv.y;
        Bs[lk + 2][le] = bv.z; Bs[lk + 3][le] = bv.w;
        __syncthreads();
        #pragma unroll
        for (int k = 0; k < BK; k++) {
            float a_[4];
            #pragma unroll
            for (int i = 0; i < 4; i++) a_[i] = sH[(ty << 2) + i][kc + k];
            float4 b4 = *(const float4*)&Bs[k][tx << 2];
            #pragma unroll
            for (int i = 0; i < 4; i++) {
                acc2[i][0] += a_[i] * b4.x; acc2[i][1] += a_[i] * b4.y;
                acc2[i][2] += a_[i] * b4.z; acc2[i][3] += a_[i] * b4.w;
            }
        }
        __syncthreads();
    }

    // ---------------- epilogue: gate by nf[src], atomic-scatter to out[dst] ----
    {
        float4 b2v = *(const float4*)(b2 + (tx << 2));
        #pragma unroll
        for (int i = 0; i < 4; i++) {
            int r = (ty << 2) + i;
            long e = e0 + r;
            if (e < E) {
                int s  = sSrc[r];
                int dd = sDst[r];
                float4 nf4 = *(const float4*)(nf + (long)s * D_DIM + (tx << 2));
                float m0 = (acc2[i][0] + b2v.x) * nf4.x;
                float m1 = (acc2[i][1] + b2v.y) * nf4.y;
                float m2 = (acc2[i][2] + b2v.z) * nf4.z;
                float m3 = (acc2[i][3] + b2v.w) * nf4.w;
                float* op = out + (long)dd * D_DIM + (tx << 2);
                atomicAdd(op + 0, m0);
                atomicAdd(op + 1, m1);
                atomicAdd(op + 2, m2);
                atomicAdd(op + 3, m3);
            }
        }
    }
}

extern "C" void kernel_launch(void* const* d_in, const int* in_sizes, int n_in,
                              void* d_out, int out_size) {
    const float* rbf = (const float*)d_in[0];
    const float* nf  = (const float*)d_in[1];
    const int*   src = (const int*)d_in[2];
    const int*   dst = (const int*)d_in[3];
    const float* W1  = (const float*)d_in[4];
    const float* b1  = (const float*)d_in[5];
    const float* W2  = (const float*)d_in[6];
    const float* b2  = (const float*)d_in[7];
    float* out = (float*)d_out;

    const int E = in_sizes[2];          // number of edges (src count)

    // zero the output (harness poisons it)
    int n4 = out_size / 4;
    zero_out_kernel<<<(n4 + 255) / 256, 256>>>((float4*)out, n4);

    int grid = (E + BM - 1) / BM;
    cfconv_kernel<<<grid, 256>>>(rbf, nf, src, dst, W1, b1, W2, b2, out, E);
}

// round 3
// speedup vs baseline: 1.4928x; 1.4928x over previous
#include <cuda_runtime.h>
#include <cstdint>

// CFConv fused, TF32 tensor-core version.
// h  = softplus_b05(rbf @ W1^T + b1)   [E,128] x [64,128]^T -> [E,64]
// g  = h @ W2^T + b2                   [E,64]  x [64,64]^T  -> [E,64]
// out[dst[e]] += node_feats[src[e]] * g[e]
//
// Tile: 128 edges x 64 dims per 128-thread block (4 warps, each 32 edges x 64 dims).
// mma.sync.m16n8k8.tf32, operands converted to tf32 once at smem staging.

constexpr int BM      = 128;   // edges per block
constexpr int THREADS = 128;   // 4 warps

// smem layout (32-bit words), strides chosen so (stride % 32) == 4 -> conflict-free frags
constexpr int W1_STRIDE = 132;                   // [64][132]
constexpr int W2_STRIDE = 68;                    // [64][68]
constexpr int A_STRIDE  = 36;                    // [128][36]  (K-chunk of 32)
constexpr int H_STRIDE  = 68;                    // [128][68]
constexpr int OFF_W1  = 0;
constexpr int OFF_W2  = OFF_W1 + 64 * W1_STRIDE;          // 8448
constexpr int OFF_A   = OFF_W2 + 64 * W2_STRIDE;          // 12800
constexpr int OFF_H   = OFF_A  + BM * A_STRIDE;           // 17408
constexpr int OFF_SRC = OFF_H  + BM * H_STRIDE;           // 26112
constexpr int OFF_DST = OFF_SRC + BM;                     // 26240
constexpr int SMEM_WORDS = OFF_DST + BM;                  // 26368
constexpr int SMEM_BYTES = SMEM_WORDS * 4;                // 105472

__global__ void zero_out_kernel(float4* out4, int n4) {
    int i = blockIdx.x * blockDim.x + threadIdx.x;
    if (i < n4) out4[i] = make_float4(0.f, 0.f, 0.f, 0.f);
}

__device__ __forceinline__ uint32_t f2tf(float x) {
    uint32_t y;
    asm("cvt.rna.tf32.f32 %0, %1;" : "=r"(y) : "f"(x));
    return y;
}

__device__ __forceinline__ float softplus_b05(float x) {
    float hx = 0.5f * x;
    return (hx > 14.0f) ? x : 2.0f * log1pf(__expf(hx));
}

__device__ __forceinline__ void mma_tf32(float c[4], const uint32_t a[4],
                                         uint32_t b0, uint32_t b1) {
    asm volatile(
        "mma.sync.aligned.m16n8k8.row.col.f32.tf32.tf32.f32 "
        "{%0,%1,%2,%3}, {%4,%5,%6,%7}, {%8,%9}, {%0,%1,%2,%3};"
        : "+f"(c[0]), "+f"(c[1]), "+f"(c[2]), "+f"(c[3])
        : "r"(a[0]), "r"(a[1]), "r"(a[2]), "r"(a[3]), "r"(b0), "r"(b1));
}

__global__ __launch_bounds__(THREADS) void cfconv_tf32_kernel(
    const float* __restrict__ rbf,   // [E,128]
    const float* __restrict__ nf,    // [N,64]
    const int*   __restrict__ src,   // [E]
    const int*   __restrict__ dst,   // [E]
    const float* __restrict__ W1,    // [64,128]
    const float* __restrict__ b1,    // [64]
    const float* __restrict__ W2,    // [64,64]
    const float* __restrict__ b2,    // [64]
    float*       __restrict__ out,   // [N,64]
    int E)
{
    extern __shared__ uint32_t smem[];
    uint32_t* sW1 = smem + OFF_W1;
    uint32_t* sW2 = smem + OFF_W2;
    uint32_t* sA  = smem + OFF_A;
    float*    sH  = (float*)(smem + OFF_H);
    int*      sSrc = (int*)(smem + OFF_SRC);
    int*      sDst = (int*)(smem + OFF_DST);

    const int tid    = threadIdx.x;
    const int lane   = tid & 31;
    const int warp   = tid >> 5;
    const int gr     = lane >> 2;   // fragment row group 0..7
    const int gc     = lane & 3;    // fragment col group 0..3
    const int m_base = warp * 32;   // warp's edge offset within tile
    const long e0    = (long)blockIdx.x * BM;

    // ---- stage weights (tf32) + edge indices ----
    #pragma unroll
    for (int i = 0; i < 16; i++) {             // W1: 2048 float4
        int idx = tid + THREADS * i;
        int row = idx >> 5, c4 = idx & 31;
        float4 v = *(const float4*)(W1 + (long)row * 128 + c4 * 4);
        uint32_t* p = sW1 + row * W1_STRIDE + c4 * 4;
        p[0] = f2tf(v.x); p[1] = f2tf(v.y); p[2] = f2tf(v.z); p[3] = f2tf(v.w);
    }
    #pragma unroll
    for (int i = 0; i < 8; i++) {              // W2: 1024 float4
        int idx = tid + THREADS * i;
        int row = idx >> 4, c4 = idx & 15;
        float4 v = *(const float4*)(W2 + (long)row * 64 + c4 * 4);
        uint32_t* p = sW2 + row * W2_STRIDE + c4 * 4;
        p[0] = f2tf(v.x); p[1] = f2tf(v.y); p[2] = f2tf(v.z); p[3] = f2tf(v.w);
    }
    {
        long e = e0 + tid;
        sSrc[tid] = (e < E) ? src[e] : 0;
        sDst[tid] = (e < E) ? dst[e] : 0;
    }

    // ---- GEMM1: acc = rbf @ W1^T  (K=128, chunks of 32) ----
    float acc[2][8][4] = {};
    for (int kc = 0; kc < 128; kc += 32) {
        __syncthreads();
        // stage rbf chunk [128][32] -> tf32
        #pragma unroll
        for (int i = 0; i < 8; i++) {          // 1024 float4
            int idx = tid + THREADS * i;
            int row = idx >> 3, c4 = idx & 7;
            long e = e0 + row;
            float4 v = (e < E) ? *(const float4*)(rbf + e * 128 + kc + c4 * 4)
                               : make_float4(0.f, 0.f, 0.f, 0.f);
            uint32_t* p = sA + row * A_STRIDE + c4 * 4;
            p[0] = f2tf(v.x); p[1] = f2tf(v.y); p[2] = f2tf(v.z); p[3] = f2tf(v.w);
        }
        __syncthreads();

        #pragma unroll
        for (int ks = 0; ks < 32; ks += 8) {
            uint32_t a[2][4];
            #pragma unroll
            for (int mt = 0; mt < 2; mt++) {
                const uint32_t* base = sA + (m_base + mt * 16 + gr) * A_STRIDE + ks + gc;
                a[mt][0] = base[0];
                a[mt][1] = base[8 * A_STRIDE];
                a[mt][2] = base[4];
                a[mt][3] = base[8 * A_STRIDE + 4];
            }
            #pragma unroll
            for (int nt = 0; nt < 8; nt++) {
                const uint32_t* bb = sW1 + (nt * 8 + gr) * W1_STRIDE + kc + ks + gc;
                uint32_t b0 = bb[0], b1v = bb[4];
                mma_tf32(acc[0][nt], a[0], b0, b1v);
                mma_tf32(acc[1][nt], a[1], b0, b1v);
            }
        }
    }
    __syncthreads();

    // ---- bias + softplus, stage h (tf32) into sH ----
    #pragma unroll
    for (int nt = 0; nt < 8; nt++) {
        int col0 = nt * 8 + 2 * gc;
        float bc0 = __ldg(b1 + col0), bc1 = __ldg(b1 + col0 + 1);
        #pragma unroll
        for (int mt = 0; mt < 2; mt++) {
            int r0 = m_base + mt * 16 + gr;
            float* p0 = sH + r0 * H_STRIDE + col0;
            float* p1 = sH + (r0 + 8) * H_STRIDE + col0;
            p0[0] = __uint_as_float(f2tf(softplus_b05(acc[mt][nt][0] + bc0)));
            p0[1] = __uint_as_float(f2tf(softplus_b05(acc[mt][nt][1] + bc1)));
            p1[0] = __uint_as_float(f2tf(softplus_b05(acc[mt][nt][2] + bc0)));
            p1[1] = __uint_as_float(f2tf(softplus_b05(acc[mt][nt][3] + bc1)));
        }
    }
    __syncthreads();

    // ---- GEMM2: acc2 = h @ W2^T  (K=64) ----
    float acc2[2][8][4] = {};
    const uint32_t* sHu = (const uint32_t*)sH;
    #pragma unroll
    for (int ks = 0; ks < 64; ks += 8) {
        uint32_t a[2][4];
        #pragma unroll
        for (int mt = 0; mt < 2; mt++) {
            const uint32_t* base = sHu + (m_base + mt * 16 + gr) * H_STRIDE + ks + gc;
            a[mt][0] = base[0];
            a[mt][1] = base[8 * H_STRIDE];
            a[mt][2] = base[4];
            a[mt][3] = base[8 * H_STRIDE + 4];
        }
        #pragma unroll
        for (int nt = 0; nt < 8; nt++) {
            const uint32_t* bb = sW2 + (nt * 8 + gr) * W2_STRIDE + ks + gc;
            uint32_t b0 = bb[0], b1v = bb[4];
            mma_tf32(acc2[0][nt], a[0], b0, b1v);
            mma_tf32(acc2[1][nt], a[1], b0, b1v);
        }
    }
    __syncthreads();

    // ---- stage g = acc2 + b2 (fp32) into sH ----
    #pragma unroll
    for (int nt = 0; nt < 8; nt++) {
        int col0 = nt * 8 + 2 * gc;
        float bc0 = __ldg(b2 + col0), bc1 = __ldg(b2 + col0 + 1);
        #pragma unroll
        for (int mt = 0; mt < 2; mt++) {
            int r0 = m_base + mt * 16 + gr;
            float* p0 = sH + r0 * H_STRIDE + col0;
            float* p1 = sH + (r0 + 8) * H_STRIDE + col0;
            p0[0] = acc2[mt][nt][0] + bc0;
            p0[1] = acc2[mt][nt][1] + bc1;
            p1[0] = acc2[mt][nt][2] + bc0;
            p1[1] = acc2[mt][nt][3] + bc1;
        }
    }
    __syncthreads();

    // ---- epilogue: msg = nf[src] * g, vector atomic scatter to out[dst] ----
    #pragma unroll
    for (int i = 0; i < 16; i++) {             // 2048 float4 = 128 edges x 16 f4
        int idx = tid + THREADS * i;
        int er  = idx >> 4;                     // local edge
        int col = (idx & 15) * 4;
        long e = e0 + er;
        if (e < E) {
            int s = sSrc[er], d = sDst[er];
            float4 g4  = *(const float4*)(sH + er * H_STRIDE + col);
            float4 nf4 = *(const float4*)(nf + (long)s * 64 + col);
            float x = g4.x * nf4.x, y = g4.y * nf4.y;
            float z = g4.z * nf4.z, w = g4.w * nf4.w;
            float* p = out + (long)d * 64 + col;
            asm volatile("red.global.add.v4.f32 [%0], {%1,%2,%3,%4};"
                         :: "l"(p), "f"(x), "f"(y), "f"(z), "f"(w) : "memory");
        }
    }
}

extern "C" void kernel_launch(void* const* d_in, const int* in_sizes, int n_in,
                              void* d_out, int out_size) {
    const float* rbf = (const float*)d_in[0];
    const float* nf  = (const float*)d_in[1];
    const int*   src = (const int*)d_in[2];
    const int*   dst = (const int*)d_in[3];
    const float* W1  = (const float*)d_in[4];
    const float* b1  = (const float*)d_in[5];
    const float* W2  = (const float*)d_in[6];
    const float* b2  = (const float*)d_in[7];
    float* out = (float*)d_out;

    const int E = in_sizes[2];

    cudaFuncSetAttribute(cfconv_tf32_kernel,
                         cudaFuncAttributeMaxDynamicSharedMemorySize, SMEM_BYTES);

    int n4 = out_size / 4;
    zero_out_kernel<<<(n4 + 255) / 256, 256>>>((float4*)out, n4);

    int grid = (E + BM - 1) / BM;
    cfconv_tf32_kernel<<<grid, THREADS, SMEM_BYTES>>>(
        rbf, nf, src, dst, W1, b1, W2, b2, out, E);
}

// round 4
// speedup vs baseline: 2.1746x; 1.4567x over previous
#include <cuda_runtime.h>
#include <cstdint>

// CFConv fused, TF32 tensor cores, register-resident h (shuffle transpose),
// cp.async double-buffered rbf staging, vector atomic scatter.
//
// h  = softplus_b05(rbf @ W1^T + b1)   [E,128] x [64,128]^T -> [E,64]
// g  = h @ W2^T + b2                   [E,64]  x [64,64]^T  -> [E,64]
// out[dst[e]] += node_feats[src[e]] * g[e]
//
// 128 threads (4 warps), 128 edges/block (32 edges per warp, mt=2 m16-tiles).

constexpr int BM      = 128;
constexpr int THREADS = 128;

constexpr int W1_STRIDE = 132;   // 64 x 132 words (tf32), conflict-free frags
constexpr int W2_STRIDE = 68;    // 64 x 68
constexpr int A_STRIDE  = 20;    // K-chunk 16 + pad 4 (raw fp32)

constexpr int OFF_W1  = 0;
constexpr int OFF_W2  = OFF_W1 + 64 * W1_STRIDE;        // 8448
constexpr int OFF_A   = OFF_W2 + 64 * W2_STRIDE;        // 12800
constexpr int OFF_B   = OFF_A + 2 * BM * A_STRIDE;      // 17920 (b1|b2, 128 words)
constexpr int OFF_SRC = OFF_B + 128;                    // 18048
constexpr int OFF_DST = OFF_SRC + BM;                   // 18176
constexpr int SMEM_WORDS = OFF_DST + BM;                // 18304
constexpr int SMEM_BYTES = SMEM_WORDS * 4;              // 73216 -> 3 CTAs/SM

__global__ void zero_out_kernel(float4* out4, int n4) {
    int i = blockIdx.x * blockDim.x + threadIdx.x;
    if (i < n4) out4[i] = make_float4(0.f, 0.f, 0.f, 0.f);
}

__device__ __forceinline__ uint32_t f2tf(float x) {
    uint32_t y;
    asm("cvt.rna.tf32.f32 %0, %1;" : "=r"(y) : "f"(x));
    return y;
}

__device__ __forceinline__ float softplus_b05(float x) {
    float hx = 0.5f * x;
    return (hx > 14.0f) ? x : 2.0f * log1pf(__expf(hx));
}

__device__ __forceinline__ void mma_tf32(float c[4], const uint32_t a[4],
                                         uint32_t b0, uint32_t b1) {
    asm volatile(
        "mma.sync.aligned.m16n8k8.row.col.f32.tf32.tf32.f32 "
        "{%0,%1,%2,%3}, {%4,%5,%6,%7}, {%8,%9}, {%0,%1,%2,%3};"
        : "+f"(c[0]), "+f"(c[1]), "+f"(c[2]), "+f"(c[3])
        : "r"(a[0]), "r"(a[1]), "r"(a[2]), "r"(a[3]), "r"(b0), "r"(b1));
}

__device__ __forceinline__ void cp_async16(void* sdst, const void* gsrc, int szbytes) {
    uint32_t sa = (uint32_t)__cvta_generic_to_shared(sdst);
    asm volatile("cp.async.cg.shared.global [%0], [%1], 16, %2;"
                 :: "r"(sa), "l"(gsrc), "r"(szbytes));
}

__global__ void __launch_bounds__(THREADS, 3) cfconv_tf32_kernel(
    const float* __restrict__ rbf,   // [E,128]
    const float* __restrict__ nf,    // [N,64]
    const int*   __restrict__ src,   // [E]
    const int*   __restrict__ dst,   // [E]
    const float* __restrict__ W1,    // [64,128]
    const float* __restrict__ b1,    // [64]
    const float* __restrict__ W2,    // [64,64]
    const float* __restrict__ b2,    // [64]
    float*       __restrict__ out,   // [N,64]
    int E)
{
    extern __shared__ uint32_t smem[];
    uint32_t* sW1 = smem + OFF_W1;
    uint32_t* sW2 = smem + OFF_W2;
    float*    sA  = (float*)(smem + OFF_A);     // 2 x [128][20]
    float*    sB  = (float*)(smem + OFF_B);     // b1[0:64], b2[64:128]
    int*      sSrc = (int*)(smem + OFF_SRC);
    int*      sDst = (int*)(smem + OFF_DST);

    const int tid  = threadIdx.x;
    const int lane = tid & 31;
    const int warp = tid >> 5;
    const int gr   = lane >> 2;       // 0..7
    const int gc   = lane & 3;        // 0..3
    const int wrow = warp * 32;       // warp's 32 edges within tile
    const long e0  = (long)blockIdx.x * BM;
    const unsigned FULL = 0xffffffffu;

    // ---- kick off cp.async prefetch of rbf chunk 0 ----
    {
        #pragma unroll
        for (int i = 0; i < 4; i++) {
            int idx = tid + THREADS * i;          // 512 f4 per chunk
            int row = idx >> 2, c4 = idx & 3;
            long e = e0 + row;
            long ec = (e < E) ? e : 0;
            cp_async16(sA + row * A_STRIDE + c4 * 4,
                       rbf + ec * 128 + c4 * 4, (e < E) ? 16 : 0);
        }
        asm volatile("cp.async.commit_group;");
    }

    // ---- stage weights (tf32), biases, indices (overlaps cp.async) ----
    #pragma unroll
    for (int i = 0; i < 16; i++) {                // W1: 2048 f4
        int idx = tid + THREADS * i;
        int row = idx >> 5, c4 = idx & 31;
        float4 v = *(const float4*)(W1 + (long)row * 128 + c4 * 4);
        uint4 u = make_uint4(f2tf(v.x), f2tf(v.y), f2tf(v.z), f2tf(v.w));
        *(uint4*)(sW1 + row * W1_STRIDE + c4 * 4) = u;
    }
    #pragma unroll
    for (int i = 0; i < 8; i++) {                 // W2: 1024 f4
        int idx = tid + THREADS * i;
        int row = idx >> 4, c4 = idx & 15;
        float4 v = *(const float4*)(W2 + (long)row * 64 + c4 * 4);
        uint4 u = make_uint4(f2tf(v.x), f2tf(v.y), f2tf(v.z), f2tf(v.w));
        *(uint4*)(sW2 + row * W2_STRIDE + c4 * 4) = u;
    }
    if (tid < 64) { sB[tid] = b1[tid]; sB[64 + tid] = b2[tid]; }
    {
        long e = e0 + tid;
        sSrc[tid] = (e < E) ? src[e] : 0;
        sDst[tid] = (e < E) ? dst[e] : 0;
    }

    // ---- GEMM1: acc = rbf @ W1^T, K=128 in 8 chunks of 16, double-buffered ----
    float acc[2][8][4] = {};
    #pragma unroll
    for (int c = 0; c < 8; c++) {
        asm volatile("cp.async.wait_group 0;");
        __syncthreads();
        if (c < 7) {
            float* buf = sA + ((c + 1) & 1) * BM * A_STRIDE;
            #pragma unroll
            for (int i = 0; i < 4; i++) {
                int idx = tid + THREADS * i;
                int row = idx >> 2, c4 = idx & 3;
                long e = e0 + row;
                long ec = (e < E) ? e : 0;
                cp_async16(buf + row * A_STRIDE + c4 * 4,
                           rbf + ec * 128 + (c + 1) * 16 + c4 * 4, (e < E) ? 16 : 0);
            }
            asm volatile("cp.async.commit_group;");
        }
        const float* buf = sA + (c & 1) * BM * A_STRIDE;
        #pragma unroll
        for (int ks = 0; ks < 2; ks++) {
            const int k = ks * 8;
            uint32_t a[2][4];
            #pragma unroll
            for (int mt = 0; mt < 2; mt++) {
                const float* p = buf + (wrow + mt * 16 + gr) * A_STRIDE + k + gc;
                a[mt][0] = f2tf(p[0]);
                a[mt][1] = f2tf(p[8 * A_STRIDE]);
                a[mt][2] = f2tf(p[4]);
                a[mt][3] = f2tf(p[8 * A_STRIDE + 4]);
            }
            #pragma unroll
            for (int nt = 0; nt < 8; nt++) {
                const uint32_t* bb = sW1 + (nt * 8 + gr) * W1_STRIDE + c * 16 + k + gc;
                uint32_t b0 = bb[0], b1r = bb[4];
                mma_tf32(acc[0][nt], a[0], b0, b1r);
                mma_tf32(acc[1][nt], a[1], b0, b1r);
            }
        }
    }

    // ---- bias + softplus + tf32, in place (bit pattern stored as float) ----
    #pragma unroll
    for (int nt = 0; nt < 8; nt++) {
        float bc0 = sB[nt * 8 + 2 * gc], bc1 = sB[nt * 8 + 2 * gc + 1];
        #pragma unroll
        for (int mt = 0; mt < 2; mt++) {
            acc[mt][nt][0] = __uint_as_float(f2tf(softplus_b05(acc[mt][nt][0] + bc0)));
            acc[mt][nt][1] = __uint_as_float(f2tf(softplus_b05(acc[mt][nt][1] + bc1)));
            acc[mt][nt][2] = __uint_as_float(f2tf(softplus_b05(acc[mt][nt][2] + bc0)));
            acc[mt][nt][3] = __uint_as_float(f2tf(softplus_b05(acc[mt][nt][3] + bc1)));
        }
    }

    // ---- GEMM2: acc2 = h @ W2^T; A-frags from acc via shuffle transpose ----
    float acc2[2][8][4] = {};
    const int slo = (lane & 28) | (gc >> 1);
    const bool odd = (gc & 1);
    #pragma unroll
    for (int kt = 0; kt < 8; kt++) {
        uint32_t a[2][4];
        #pragma unroll
        for (int mt = 0; mt < 2; mt++) {
            uint32_t c0 = __float_as_uint(acc[mt][kt][0]);
            uint32_t c1 = __float_as_uint(acc[mt][kt][1]);
            uint32_t c2 = __float_as_uint(acc[mt][kt][2]);
            uint32_t c3 = __float_as_uint(acc[mt][kt][3]);
            uint32_t t0 = __shfl_sync(FULL, c0, slo);
            uint32_t t1 = __shfl_sync(FULL, c1, slo);
            uint32_t t2 = __shfl_sync(FULL, c2, slo);
            uint32_t t3 = __shfl_sync(FULL, c3, slo);
            uint32_t u0 = __shfl_sync(FULL, c0, slo + 2);
            uint32_t u1 = __shfl_sync(FULL, c1, slo + 2);
            uint32_t u2 = __shfl_sync(FULL, c2, slo + 2);
            uint32_t u3 = __shfl_sync(FULL, c3, slo + 2);
            a[mt][0] = odd ? t1 : t0;   // h[gr][8kt+gc]
            a[mt][1] = odd ? t3 : t2;   // h[gr+8][8kt+gc]
            a[mt][2] = odd ? u1 : u0;   // h[gr][8kt+gc+4]
            a[mt][3] = odd ? u3 : u2;   // h[gr+8][8kt+gc+4]
        }
        #pragma unroll
        for (int nt = 0; nt < 8; nt++) {
            const uint32_t* bb = sW2 + (nt * 8 + gr) * W2_STRIDE + kt * 8 + gc;
            uint32_t b0 = bb[0], b1r = bb[4];
            mma_tf32(acc2[0][nt], a[0], b0, b1r);
            mma_tf32(acc2[1][nt], a[1], b0, b1r);
        }
    }

    // ---- epilogue: bias2, pair-exchange to float4 runs, gate by nf[src],
    //      red.global.add.v4 scatter to out[dst] ----
    #pragma unroll
    for (int mt = 0; mt < 2; mt++) {
        int r0 = wrow + mt * 16 + gr;
        int row = odd ? (r0 + 8) : r0;          // this lane's output row
        long e = e0 + row;
        bool valid = (e < E);
        int s = sSrc[row], d = sDst[row];
        const float* nfr = nf + (long)s * 64;
        float* outr = out + (long)d * 64;
        #pragma unroll
        for (int nt = 0; nt < 8; nt++) {
            float bc0 = sB[64 + nt * 8 + 2 * gc], bc1 = sB[64 + nt * 8 + 2 * gc + 1];
            float g0 = acc2[mt][nt][0] + bc0, g1 = acc2[mt][nt][1] + bc1;
            float g2 = acc2[mt][nt][2] + bc0, g3 = acc2[mt][nt][3] + bc1;
            float x0 = __shfl_xor_sync(FULL, g0, 1);
            float x1 = __shfl_xor_sync(FULL, g1, 1);
            float x2 = __shfl_xor_sync(FULL, g2, 1);
            float x3 = __shfl_xor_sync(FULL, g3, 1);
            float v0, v1, v2, v3;
            if (odd) { v0 = x2; v1 = x3; v2 = g2; v3 = g3; }   // row r0+8
            else     { v0 = g0; v1 = g1; v2 = x0; v3 = x1; }   // row r0
            int col = nt * 8 + 4 * (gc >> 1);
            if (valid) {
                float4 nf4 = *(const float4*)(nfr + col);
                v0 *= nf4.x; v1 *= nf4.y; v2 *= nf4.z; v3 *= nf4.w;
                asm volatile("red.global.add.v4.f32 [%0], {%1,%2,%3,%4};"
                             :: "l"(outr + col), "f"(v0), "f"(v1), "f"(v2), "f"(v3)
                             : "memory");
            }
        }
    }
}

extern "C" void kernel_launch(void* const* d_in, const int* in_sizes, int n_in,
                              void* d_out, int out_size) {
    const float* rbf = (const float*)d_in[0];
    const float* nf  = (const float*)d_in[1];
    const int*   src = (const int*)d_in[2];
    const int*   dst = (const int*)d_in[3];
    const float* W1  = (const float*)d_in[4];
    const float* b1  = (const float*)d_in[5];
    const float* W2  = (const float*)d_in[6];
    const float* b2  = (const float*)d_in[7];
    float* out = (float*)d_out;

    const int E = in_sizes[2];

    cudaFuncSetAttribute(cfconv_tf32_kernel,
                         cudaFuncAttributeMaxDynamicSharedMemorySize, SMEM_BYTES);

    int n4 = out_size / 4;
    zero_out_kernel<<<(n4 + 255) / 256, 256>>>((float4*)out, n4);

    int grid = (E + BM - 1) / BM;
    cfconv_tf32_kernel<<<grid, THREADS, SMEM_BYTES>>>(
        rbf, nf, src, dst, W1, b1, W2, b2, out, E);
}

// round 5
// speedup vs baseline: 3.5718x; 1.6425x over previous
#include <cuda_runtime.h>
#include <cuda_fp16.h>
#include <cstdint>

// CFConv fused, FP16 tensor cores (m16n8k16, fp32 accum).
// h  = softplus_b05(rbf @ W1^T + b1)   [E,128] x [64,128]^T -> [E,64]
// g  = h @ W2^T + b2                   [E,64]  x [64,64]^T  -> [E,64]
// out[dst[e]] += node_feats[src[e]] * g[e]
//
// 128 threads (4 warps), 128 edges/block. GEMM1 C-frag == GEMM2 A-frag layout
// (pairs along k), so h never leaves registers: no shuffles, no smem roundtrip.

constexpr int BM      = 128;
constexpr int THREADS = 128;

// strides in 32-bit words (half2 granularity for fp16 tiles)
constexpr int W1S = 68;   // 64 half2 + 4 pad  -> bank = 4*gr + gc, conflict-free
constexpr int W2S = 36;   // 32 half2 + 4 pad
constexpr int AS  = 12;   // 8 half2 + 4 pad   -> bank = 12*row mod 32 multiples of 4

constexpr int OFF_W1  = 0;
constexpr int OFF_W2  = OFF_W1 + 64 * W1S;          // 4352
constexpr int OFF_A   = OFF_W2 + 64 * W2S;          // 6656 (2 buffers x 128 x 12)
constexpr int OFF_B   = OFF_A + 2 * BM * AS;        // 9728  (b1 | b2, fp32)
constexpr int OFF_SRC = OFF_B + 128;                // 9856
constexpr int OFF_DST = OFF_SRC + BM;               // 9984
constexpr int SMEM_WORDS = OFF_DST + BM;            // 10112
constexpr int SMEM_BYTES = SMEM_WORDS * 4;          // 40448 -> smem allows 5 CTAs/SM

__global__ void zero_out_kernel(float4* out4, int n4) {
    int i = blockIdx.x * blockDim.x + threadIdx.x;
    if (i < n4) out4[i] = make_float4(0.f, 0.f, 0.f, 0.f);
}

__device__ __forceinline__ float softplus_b05(float x) {
    // 2*log(1+exp(0.5x)); linear for 0.5x>14. fast-math exp/log, error << 1e-3 budget.
    float hx = 0.5f * x;
    return (hx > 14.0f) ? x : 2.0f * __logf(1.0f + __expf(hx));
}

__device__ __forceinline__ uint32_t pack_h2(float lo, float hi) {
    __half2 p = __floats2half2_rn(make_float2(lo, hi).x, make_float2(lo, hi).y);
    return *reinterpret_cast<uint32_t*>(&p);
}

__device__ __forceinline__ void mma_f16(float c[4], const uint32_t a[4],
                                        uint32_t b0, uint32_t b1) {
    asm volatile(
        "mma.sync.aligned.m16n8k16.row.col.f32.f16.f16.f32 "
        "{%0,%1,%2,%3}, {%4,%5,%6,%7}, {%8,%9}, {%0,%1,%2,%3};"
        : "+f"(c[0]), "+f"(c[1]), "+f"(c[2]), "+f"(c[3])
        : "r"(a[0]), "r"(a[1]), "r"(a[2]), "r"(a[3]), "r"(b0), "r"(b1));
}

__global__ void __launch_bounds__(THREADS, 4) cfconv_f16_kernel(
    const float* __restrict__ rbf,   // [E,128]
    const float* __restrict__ nf,    // [N,64]
    const int*   __restrict__ src,   // [E]
    const int*   __restrict__ dst,   // [E]
    const float* __restrict__ W1,    // [64,128]
    const float* __restrict__ b1,    // [64]
    const float* __restrict__ W2,    // [64,64]
    const float* __restrict__ b2,    // [64]
    float*       __restrict__ out,   // [N,64]
    int E)
{
    extern __shared__ uint32_t smem[];
    uint32_t* sW1 = smem + OFF_W1;   // half2 rows [64][68]
    uint32_t* sW2 = smem + OFF_W2;   // half2 rows [64][36]
    uint32_t* sA  = smem + OFF_A;    // 2 x [128][12] half2
    float*    sB  = (float*)(smem + OFF_B);
    int*      sSrc = (int*)(smem + OFF_SRC);
    int*      sDst = (int*)(smem + OFF_DST);

    const int tid  = threadIdx.x;
    const int lane = tid & 31;
    const int warp = tid >> 5;
    const int gr   = lane >> 2;     // 0..7
    const int gc   = lane & 3;      // 0..3
    const int wrow = warp * 32;
    const long e0  = (long)blockIdx.x * BM;
    const unsigned FULL = 0xffffffffu;
    const bool odd = (gc & 1);

    // ---- stage weights as half2, biases, indices ----
    #pragma unroll
    for (int i = 0; i < 16; i++) {               // W1: 2048 float4
        int idx = tid + THREADS * i;
        int row = idx >> 5, c4 = idx & 31;
        float4 v = *(const float4*)(W1 + (long)row * 128 + c4 * 4);
        uint2 u = make_uint2(pack_h2(v.x, v.y), pack_h2(v.z, v.w));
        *(uint2*)(sW1 + row * W1S + c4 * 2) = u;
    }
    #pragma unroll
    for (int i = 0; i < 8; i++) {                // W2: 1024 float4
        int idx = tid + THREADS * i;
        int row = idx >> 4, c4 = idx & 15;
        float4 v = *(const float4*)(W2 + (long)row * 64 + c4 * 4);
        uint2 u = make_uint2(pack_h2(v.x, v.y), pack_h2(v.z, v.w));
        *(uint2*)(sW2 + row * W2S + c4 * 2) = u;
    }
    if (tid < 64) { sB[tid] = b1[tid]; sB[64 + tid] = b2[tid]; }
    {
        long e = e0 + tid;
        sSrc[tid] = (e < E) ? src[e] : 0;
        sDst[tid] = (e < E) ? dst[e] : 0;
    }

    // rbf staging map: thread covers 4 float4 (4 rows, 4 cols each) per chunk
    int arow[4], acol;
    {
        // idx = tid + 128*i : row = idx>>2 (0..127), c4 = idx&3
        acol = (tid & 3) * 4;                    // float col within 16-chunk
        #pragma unroll
        for (int i = 0; i < 4; i++) arow[i] = (tid + THREADS * i) >> 2;
    }
    long eclamp[4];
    #pragma unroll
    for (int i = 0; i < 4; i++) {
        long e = e0 + arow[i];
        eclamp[i] = (e < E) ? e : 0;             // garbage rows discarded in epilogue
    }

    // ---- prefetch chunk 0 into registers ----
    float4 rg[4];
    #pragma unroll
    for (int i = 0; i < 4; i++)
        rg[i] = *(const float4*)(rbf + eclamp[i] * 128 + acol);

    // ---- GEMM1: K=128 in 8 chunks of 16, register->smem(fp16) pipeline ----
    float acc[2][8][4] = {};
    #pragma unroll
    for (int c = 0; c < 8; c++) {
        uint32_t* buf = sA + (c & 1) * BM * AS;
        #pragma unroll
        for (int i = 0; i < 4; i++) {
            uint2 u = make_uint2(pack_h2(rg[i].x, rg[i].y), pack_h2(rg[i].z, rg[i].w));
            *(uint2*)(buf + arow[i] * AS + (acol >> 1)) = u;
        }
        if (c < 7) {
            #pragma unroll
            for (int i = 0; i < 4; i++)
                rg[i] = *(const float4*)(rbf + eclamp[i] * 128 + (c + 1) * 16 + acol);
        }
        __syncthreads();

        uint32_t a[2][4];
        #pragma unroll
        for (int mt = 0; mt < 2; mt++) {
            const uint32_t* p = buf + (wrow + mt * 16 + gr) * AS + gc;
            a[mt][0] = p[0];             // k pair 2gc,2gc+1 row gr
            a[mt][1] = p[8 * AS];        // row gr+8
            a[mt][2] = p[4];             // k pair 2gc+8
            a[mt][3] = p[8 * AS + 4];
        }
        #pragma unroll
        for (int nt = 0; nt < 8; nt++) {
            const uint32_t* bb = sW1 + (nt * 8 + gr) * W1S + c * 8 + gc;
            uint32_t b0 = bb[0], b1r = bb[4];
            mma_f16(acc[0][nt], a[0], b0, b1r);
            mma_f16(acc[1][nt], a[1], b0, b1r);
        }
    }

    // ---- bias + softplus + pack: C-frags -> GEMM2 A-frags (registers only) ----
    uint32_t hA[2][4][4];
    #pragma unroll
    for (int kt = 0; kt < 4; kt++) {
        float bA0 = sB[kt * 16 + 2 * gc],     bA1 = sB[kt * 16 + 2 * gc + 1];
        float bB0 = sB[kt * 16 + 8 + 2 * gc], bB1 = sB[kt * 16 + 8 + 2 * gc + 1];
        #pragma unroll
        for (int mt = 0; mt < 2; mt++) {
            const float* cA = acc[mt][2 * kt];       // cols kt*16 + 2gc(+1)
            const float* cB = acc[mt][2 * kt + 1];   // cols kt*16 + 8 + 2gc(+1)
            hA[mt][kt][0] = pack_h2(softplus_b05(cA[0] + bA0), softplus_b05(cA[1] + bA1));
            hA[mt][kt][1] = pack_h2(softplus_b05(cA[2] + bA0), softplus_b05(cA[3] + bA1));
            hA[mt][kt][2] = pack_h2(softplus_b05(cB[0] + bB0), softplus_b05(cB[1] + bB1));
            hA[mt][kt][3] = pack_h2(softplus_b05(cB[2] + bB0), softplus_b05(cB[3] + bB1));
        }
    }

    // ---- GEMM2: acc2 = h @ W2^T, K=64 in 4 chunks of 16 ----
    float acc2[2][8][4] = {};
    #pragma unroll
    for (int kt = 0; kt < 4; kt++) {
        #pragma unroll
        for (int nt = 0; nt < 8; nt++) {
            const uint32_t* bb = sW2 + (nt * 8 + gr) * W2S + kt * 8 + gc;
            uint32_t b0 = bb[0], b1r = bb[4];
            mma_f16(acc2[0][nt], hA[0][kt], b0, b1r);
            mma_f16(acc2[1][nt], hA[1][kt], b0, b1r);
        }
    }

    // ---- epilogue: bias2, pair-exchange to float4 runs, gate nf[src], scatter ----
    #pragma unroll
    for (int mt = 0; mt < 2; mt++) {
        int r0 = wrow + mt * 16 + gr;
        int row = odd ? (r0 + 8) : r0;
        long e = e0 + row;
        bool valid = (e < E);
        int s = sSrc[row], d = sDst[row];
        const float* nfr = nf + (long)s * 64;
        float* outr = out + (long)d * 64;
        #pragma unroll
        for (int nt = 0; nt < 8; nt++) {
            float bc0 = sB[64 + nt * 8 + 2 * gc], bc1 = sB[64 + nt * 8 + 2 * gc + 1];
            float g0 = acc2[mt][nt][0] + bc0, g1 = acc2[mt][nt][1] + bc1;
            float g2 = acc2[mt][nt][2] + bc0, g3 = acc2[mt][nt][3] + bc1;
            float x0 = __shfl_xor_sync(FULL, g0, 1);
            float x1 = __shfl_xor_sync(FULL, g1, 1);
            float x2 = __shfl_xor_sync(FULL, g2, 1);
            float x3 = __shfl_xor_sync(FULL, g3, 1);
            float v0, v1, v2, v3;
            if (odd) { v0 = x2; v1 = x3; v2 = g2; v3 = g3; }   // row r0+8
            else     { v0 = g0; v1 = g1; v2 = x0; v3 = x1; }   // row r0
            int col = nt * 8 + 4 * (gc >> 1);
            if (valid) {
                float4 nf4 = *(const float4*)(nfr + col);
                v0 *= nf4.x; v1 *= nf4.y; v2 *= nf4.z; v3 *= nf4.w;
                asm volatile("red.global.add.v4.f32 [%0], {%1,%2,%3,%4};"
                             :: "l"(outr + col), "f"(v0), "f"(v1), "f"(v2), "f"(v3)
                             : "memory");
            }
        }
    }
}

extern "C" void kernel_launch(void* const* d_in, const int* in_sizes, int n_in,
                              void* d_out, int out_size) {
    const float* rbf = (const float*)d_in[0];
    const float* nf  = (const float*)d_in[1];
    const int*   src = (const int*)d_in[2];
    const int*   dst = (const int*)d_in[3];
    const float* W1  = (const float*)d_in[4];
    const float* b1  = (const float*)d_in[5];
    const float* W2  = (const float*)d_in[6];
    const float* b2  = (const float*)d_in[7];
    float* out = (float*)d_out;

    const int E = in_sizes[2];

    cudaFuncSetAttribute(cfconv_f16_kernel,
                         cudaFuncAttributeMaxDynamicSharedMemorySize, SMEM_BYTES);

    int n4 = out_size / 4;
    zero_out_kernel<<<(n4 + 255) / 256, 256>>>((float4*)out, n4);

    int grid = (E + BM - 1) / BM;
    cfconv_f16_kernel<<<grid, THREADS, SMEM_BYTES>>>(
        rbf, nf, src, dst, W1, b1, W2, b2, out, E);
}